// round 6
// baseline (speedup 1.0000x reference)
#include <cuda_runtime.h>
#include <cuda.h>
#include <cuda_bf16.h>
#include <math.h>
#include <stdint.h>

#define BB 4
#define LL 2048
#define DD 1024
#define HH 16
#define DHH 64
#define NTOK (BB*LL)   // 8192 rows
#define D3  (3*DD)     // 3072

// ---------------- scratch (device globals; no allocation allowed) ----------------
__device__ __align__(16) __nv_bfloat16 g_h_hi  [NTOK*DD];
__device__ __align__(16) __nv_bfloat16 g_h_lo  [NTOK*DD];
__device__ __align__(16) __nv_bfloat16 g_qkv_hi[NTOK*D3];
__device__ __align__(16) __nv_bfloat16 g_qkv_lo[NTOK*D3];
__device__ __align__(16) __nv_bfloat16 g_ln2_hi[NTOK*DD];
__device__ __align__(16) __nv_bfloat16 g_ln2_lo[NTOK*DD];
__device__ __align__(16) __nv_bfloat16 g_mlp_hi[NTOK*DD];
__device__ __align__(16) __nv_bfloat16 g_mlp_lo[NTOK*DD];
__device__ __align__(16) __nv_bfloat16 g_wqkv_hi[3*DD*DD];
__device__ __align__(16) __nv_bfloat16 g_wqkv_lo[3*DD*DD];
__device__ __align__(16) __nv_bfloat16 g_w1_hi[DD*DD];
__device__ __align__(16) __nv_bfloat16 g_w1_lo[DD*DD];
__device__ __align__(16) __nv_bfloat16 g_w2_hi[DD*DD];
__device__ __align__(16) __nv_bfloat16 g_w2_lo[DD*DD];
__device__ __align__(16) float g_res [NTOK*DD];
__device__ __align__(16) float g_bqkv[D3];

// ============================ helpers ============================
__device__ __forceinline__ uint32_t smem_u32(const void* p) {
    uint32_t a;
    asm("{ .reg .u64 t; cvta.to.shared.u64 t, %1; cvt.u32.u64 %0, t; }" : "=r"(a) : "l"(p));
    return a;
}
__device__ __forceinline__ void mma_bf16(float* c, const uint32_t* a, const uint32_t* b) {
    asm volatile(
        "mma.sync.aligned.m16n8k16.row.col.f32.bf16.bf16.f32 "
        "{%0,%1,%2,%3}, {%4,%5,%6,%7}, {%8,%9}, {%0,%1,%2,%3};"
        : "+f"(c[0]), "+f"(c[1]), "+f"(c[2]), "+f"(c[3])
        : "r"(a[0]), "r"(a[1]), "r"(a[2]), "r"(a[3]), "r"(b[0]), "r"(b[1]));
}
__device__ __forceinline__ void ldsm_x4(uint32_t* r, uint32_t addr) {
    asm volatile("ldmatrix.sync.aligned.m8n8.x4.shared.b16 {%0,%1,%2,%3}, [%4];"
        : "=r"(r[0]), "=r"(r[1]), "=r"(r[2]), "=r"(r[3]) : "r"(addr));
}
__device__ __forceinline__ void ldsm_x4_t(uint32_t* r, uint32_t addr) {
    asm volatile("ldmatrix.sync.aligned.m8n8.x4.trans.shared.b16 {%0,%1,%2,%3}, [%4];"
        : "=r"(r[0]), "=r"(r[1]), "=r"(r[2]), "=r"(r[3]) : "r"(addr));
}
__device__ __forceinline__ void cp16(uint32_t dst, const void* src) {
    asm volatile("cp.async.cg.shared.global [%0], [%1], 16;" :: "r"(dst), "l"(src));
}
#define CP_COMMIT() asm volatile("cp.async.commit_group;" ::: "memory")
#define CP_WAIT0()  asm volatile("cp.async.wait_group 0;" ::: "memory")

// hi/lo bf16 split of a float4 -> two 8B stores each
__device__ __forceinline__ void cvt_store(__nv_bfloat16* hi, __nv_bfloat16* lo, float4 a) {
    __nv_bfloat162 h0 = __floats2bfloat162_rn(a.x, a.y);
    __nv_bfloat162 h1 = __floats2bfloat162_rn(a.z, a.w);
    __nv_bfloat162 l0 = __floats2bfloat162_rn(a.x - __bfloat162float(__low2bfloat16(h0)),
                                              a.y - __bfloat162float(__high2bfloat16(h0)));
    __nv_bfloat162 l1 = __floats2bfloat162_rn(a.z - __bfloat162float(__low2bfloat16(h1)),
                                              a.w - __bfloat162float(__high2bfloat16(h1)));
    *(__nv_bfloat162*)(hi)     = h0;
    *(__nv_bfloat162*)(hi + 2) = h1;
    *(__nv_bfloat162*)(lo)     = l0;
    *(__nv_bfloat162*)(lo + 2) = l1;
}
__device__ __forceinline__ void pack_hilo(uint32_t& ph, uint32_t& pl, float v0, float v1) {
    __nv_bfloat162 hh = __floats2bfloat162_rn(v0, v1);
    float f0 = __bfloat162float(__low2bfloat16(hh));
    float f1 = __bfloat162float(__high2bfloat16(hh));
    __nv_bfloat162 ll = __floats2bfloat162_rn(v0 - f0, v1 - f1);
    ph = *(uint32_t*)&hh;
    pl = *(uint32_t*)&ll;
}

// ============ bf16x3 GEMM, bf16 hi/lo inputs, cp.async double-buffered ============
#define GS_STRIDE 40                     // bf16 per smem row (80B)
#define GT_BYTES  (128*GS_STRIDE*2)      // 10240 per tensor tile
#define GSTAGE_BYTES (4*GT_BYTES)
#define BGEMM_SMEM (2*GSTAGE_BYTES)      // 81920

template<int ACT, bool RES, bool SPLIT>
__global__ void __launch_bounds__(256, 2)
bgemm_kernel(const __nv_bfloat16* __restrict__ Ah, const __nv_bfloat16* __restrict__ Al,
             const __nv_bfloat16* __restrict__ Bh, const __nv_bfloat16* __restrict__ Bl,
             const float* __restrict__ bias, const float* __restrict__ res,
             float* __restrict__ Cf, __nv_bfloat16* __restrict__ Ch,
             __nv_bfloat16* __restrict__ Cl, int M, int N, int K)
{
    extern __shared__ char dsm[];
    const uint32_t sb = smem_u32(dsm);

    const int tid  = threadIdx.x;
    const int wid  = tid >> 5;
    const int lane = tid & 31;
    const int wm   = wid >> 2;
    const int wn   = wid & 3;
    const int row0 = blockIdx.y * 128;
    const int col0 = blockIdx.x * 128;

    float acc[4][4][4];
    #pragma unroll
    for (int i = 0; i < 4; i++)
        #pragma unroll
        for (int j = 0; j < 4; j++)
            #pragma unroll
            for (int q = 0; q < 4; q++) acc[i][j][q] = 0.f;

    const uint32_t aoff = (uint32_t)(((lane & 15) * GS_STRIDE + ((lane >> 4) & 1) * 8) * 2);
    const int nkt = K / 32;

    auto load_stage = [&](int i, int buf) {
        uint32_t s0 = sb + (uint32_t)buf * GSTAGE_BYTES;
        int kt = i * 32;
        #pragma unroll
        for (int u = 0; u < 2; u++) {
            int c   = tid + u * 256;          // 0..511
            int row = c >> 2;
            int ch  = c & 3;                  // 16B unit
            uint32_t so = (uint32_t)(row * (GS_STRIDE * 2) + ch * 16);
            size_t ga = (size_t)(row0 + row) * K + kt + ch * 8;
            size_t gb = (size_t)(col0 + row) * K + kt + ch * 8;
            cp16(s0 + 0 * GT_BYTES + so, Ah + ga);
            cp16(s0 + 1 * GT_BYTES + so, Al + ga);
            cp16(s0 + 2 * GT_BYTES + so, Bh + gb);
            cp16(s0 + 3 * GT_BYTES + so, Bl + gb);
        }
        CP_COMMIT();
    };

    load_stage(0, 0);

    for (int i = 0; i < nkt; i++) {
        const int b = i & 1;
        CP_WAIT0();
        __syncthreads();
        if (i + 1 < nkt) load_stage(i + 1, 1 - b);

        const uint32_t sAh = sb + (uint32_t)b * GSTAGE_BYTES;
        const uint32_t sAl = sAh + GT_BYTES;
        const uint32_t sBh = sAh + 2 * GT_BYTES;
        const uint32_t sBl = sAh + 3 * GT_BYTES;

        #pragma unroll
        for (int ks = 0; ks < 32; ks += 16) {
            uint32_t ah[4][4], al[4][4];
            #pragma unroll
            for (int mt = 0; mt < 4; mt++) {
                uint32_t ro = (uint32_t)((wm * 64 + mt * 16) * (GS_STRIDE * 2)) + (uint32_t)(ks * 2);
                ldsm_x4(ah[mt], sAh + aoff + ro);
                ldsm_x4(al[mt], sAl + aoff + ro);
            }
            #pragma unroll
            for (int ntp = 0; ntp < 2; ntp++) {
                uint32_t b4h[4], b4l[4];
                uint32_t ro = (uint32_t)((wn * 32 + ntp * 16) * (GS_STRIDE * 2)) + (uint32_t)(ks * 2);
                ldsm_x4(b4h, sBh + aoff + ro);
                ldsm_x4(b4l, sBl + aoff + ro);
                #pragma unroll
                for (int hfn = 0; hfn < 2; hfn++) {
                    int nt = ntp * 2 + hfn;
                    uint32_t bh[2] = { b4h[hfn], b4h[hfn + 2] };
                    uint32_t bl[2] = { b4l[hfn], b4l[hfn + 2] };
                    #pragma unroll
                    for (int mt = 0; mt < 4; mt++) {
                        mma_bf16(acc[mt][nt], ah[mt], bh);
                        mma_bf16(acc[mt][nt], ah[mt], bl);
                        mma_bf16(acc[mt][nt], al[mt], bh);
                    }
                }
            }
        }
    }

    const int er = lane >> 2;
    const int ec = (lane & 3) * 2;
    #pragma unroll
    for (int mt = 0; mt < 4; mt++) {
        #pragma unroll
        for (int half = 0; half < 2; half++) {
            int row = row0 + wm * 64 + mt * 16 + er + half * 8;
            #pragma unroll
            for (int nt = 0; nt < 4; nt++) {
                int col = col0 + wn * 32 + nt * 8 + ec;
                float v0 = acc[mt][nt][half * 2 + 0] + bias[col];
                float v1 = acc[mt][nt][half * 2 + 1] + bias[col + 1];
                if (ACT == 1) {
                    v0 = 0.5f * v0 * (1.0f + erff(v0 * 0.70710678118654752f));
                    v1 = 0.5f * v1 * (1.0f + erff(v1 * 0.70710678118654752f));
                }
                if (RES) {
                    const float* rp = res + (size_t)row * N;
                    v0 += rp[col]; v1 += rp[col + 1];
                }
                if (SPLIT) {
                    __nv_bfloat162 h2 = __floats2bfloat162_rn(v0, v1);
                    float f0 = __bfloat162float(__low2bfloat16(h2));
                    float f1 = __bfloat162float(__high2bfloat16(h2));
                    __nv_bfloat162 l2 = __floats2bfloat162_rn(v0 - f0, v1 - f1);
                    *(__nv_bfloat162*)(Ch + (size_t)row * N + col) = h2;
                    *(__nv_bfloat162*)(Cl + (size_t)row * N + col) = l2;
                } else {
                    float2 o; o.x = v0; o.y = v1;
                    *(float2*)(Cf + (size_t)row * N + col) = o;
                }
            }
        }
    }
}

// ---------------- weight transpose + hi/lo split ----------------
__global__ void __launch_bounds__(256)
tsplit_kernel(const float* __restrict__ in, __nv_bfloat16* __restrict__ oh,
              __nv_bfloat16* __restrict__ ol)
{
    __shared__ float t[32][33];
    int bx = blockIdx.x * 32, by = blockIdx.y * 32;
    int x = bx + threadIdx.x;
    #pragma unroll
    for (int j = 0; j < 32; j += 8)
        t[threadIdx.y + j][threadIdx.x] = in[(size_t)(by + threadIdx.y + j) * DD + x];
    __syncthreads();
    int x2 = by + threadIdx.x;
    #pragma unroll
    for (int j = 0; j < 32; j += 8) {
        float v = t[threadIdx.x][threadIdx.y + j];
        size_t o = (size_t)(bx + threadIdx.y + j) * DD + x2;
        __nv_bfloat16 h = __float2bfloat16(v);
        oh[o] = h;
        ol[o] = __float2bfloat16(v - __bfloat162float(h));
    }
}

// ---------------- LayerNorm -> bf16 hi/lo ----------------
__global__ void __launch_bounds__(256)
ln_split_kernel(const float* __restrict__ in, const float* __restrict__ gam,
                const float* __restrict__ bet, __nv_bfloat16* __restrict__ oh,
                __nv_bfloat16* __restrict__ ol)
{
    size_t base = (size_t)blockIdx.x * DD;
    int t4 = threadIdx.x * 4;
    float4 v = *(const float4*)&in[base + t4];
    float s  = v.x + v.y + v.z + v.w;
    float s2 = v.x*v.x + v.y*v.y + v.z*v.z + v.w*v.w;
    #pragma unroll
    for (int o = 16; o; o >>= 1) {
        s  += __shfl_xor_sync(0xffffffffu, s,  o);
        s2 += __shfl_xor_sync(0xffffffffu, s2, o);
    }
    __shared__ float rs[8], rs2[8];
    __shared__ float smu, srstd;
    int w = threadIdx.x >> 5, lane = threadIdx.x & 31;
    if (lane == 0) { rs[w] = s; rs2[w] = s2; }
    __syncthreads();
    if (threadIdx.x == 0) {
        float S = 0.f, S2 = 0.f;
        #pragma unroll
        for (int i = 0; i < 8; i++) { S += rs[i]; S2 += rs2[i]; }
        float mu  = S * (1.0f / DD);
        float var = S2 * (1.0f / DD) - mu * mu;
        smu = mu;
        srstd = rsqrtf(var + 1e-6f);
    }
    __syncthreads();
    float mu = smu, rstd = srstd;
    float4 g4 = *(const float4*)&gam[t4];
    float4 b4 = *(const float4*)&bet[t4];
    float4 o;
    o.x = (v.x - mu) * rstd * g4.x + b4.x;
    o.y = (v.y - mu) * rstd * g4.y + b4.y;
    o.z = (v.z - mu) * rstd * g4.z + b4.z;
    o.w = (v.w - mu) * rstd * g4.w + b4.w;
    cvt_store(oh + base + t4, ol + base + t4, o);
}

// ============ tensor-core flash attention, cp.async pipelined ============
// qkv packed [NTOK][3072]: q +0, k +1024, v +2048.
#define ATSTRIDE 72            // bf16 per smem row (144B)
#define ATEN_BYTES (64*ATSTRIDE*2)   // 9216 per tensor
// layout: Qh 0, Ql 9216, K stage0 18432 (Kh,Kl), K stage1 36864, V 55296 (Vh,Vl), mask 73728
#define AOFF_K0 18432
#define AOFF_K1 36864
#define AOFF_V  55296
#define AOFF_M  73728
#define ATT2_SMEM (AOFF_M + 2*64*4)   // 74240

__global__ void __launch_bounds__(128, 3)
attn_mma_kernel(const __nv_bfloat16* __restrict__ qkv_hi,
                const __nv_bfloat16* __restrict__ qkv_lo,
                const int* __restrict__ mask,
                const float* __restrict__ x, float* __restrict__ res)
{
    extern __shared__ char sm8[];
    const uint32_t sb = smem_u32(sm8);
    __nv_bfloat16* Qh = (__nv_bfloat16*)sm8;
    __nv_bfloat16* Ql = (__nv_bfloat16*)(sm8 + ATEN_BYTES);
    float* maskadd = (float*)(sm8 + AOFF_M);

    const int tid  = threadIdx.x;
    const int wid  = tid >> 5;
    const int lane = tid & 31;
    const int b    = blockIdx.y >> 4;
    const int h    = blockIdx.y & 15;
    const int q0   = blockIdx.x * 64;
    const int er   = lane >> 2;
    const int qc   = lane & 3;

    // cp.async loaders: per tensor 64 rows x 8 chunks of 16B -> 4 per thread
    auto load_k = [&](int kt, int buf) {
        uint32_t s0 = sb + (buf ? AOFF_K1 : AOFF_K0);
        #pragma unroll
        for (int u = 0; u < 4; u++) {
            int c = tid + u * 128;
            int row = c >> 3, ch = c & 7;
            size_t g = (size_t)(b * LL + kt + row) * D3 + DD + h * DHH + ch * 8;
            uint32_t so = (uint32_t)(row * 144 + ch * 16);
            cp16(s0 + so, qkv_hi + g);
            cp16(s0 + ATEN_BYTES + so, qkv_lo + g);
        }
        CP_COMMIT();
    };
    auto load_v = [&](int kt) {
        uint32_t s0 = sb + AOFF_V;
        #pragma unroll
        for (int u = 0; u < 4; u++) {
            int c = tid + u * 128;
            int row = c >> 3, ch = c & 7;
            size_t g = (size_t)(b * LL + kt + row) * D3 + 2 * DD + h * DHH + ch * 8;
            uint32_t so = (uint32_t)(row * 144 + ch * 16);
            cp16(s0 + so, qkv_hi + g);
            cp16(s0 + ATEN_BYTES + so, qkv_lo + g);
        }
        CP_COMMIT();
    };

    // ---- prologue: Q regular load, K(0) cp.async, mask(0) ----
    {
        int lr = tid >> 1, lc = (tid & 1) * 32;
        size_t gq = (size_t)(b * LL + q0 + lr) * D3 + h * DHH + lc;
        #pragma unroll
        for (int j = 0; j < 4; j++) {
            *(uint4*)&Qh[lr * ATSTRIDE + lc + 8*j] = *(const uint4*)(qkv_hi + gq + 8*j);
            *(uint4*)&Ql[lr * ATSTRIDE + lc + 8*j] = *(const uint4*)(qkv_lo + gq + 8*j);
        }
    }
    load_k(0, 0);
    if (tid < 64)
        maskadd[tid] = (1.0f - (float)mask[b * LL + tid]) * (-1e30f);
    __syncthreads();

    // ---- persistent Q fragments ----
    const uint32_t aoff = (uint32_t)(((lane & 15) * ATSTRIDE + ((lane >> 4) & 1) * 8) * 2);
    uint32_t qh[4][4], qlo[4][4];
    #pragma unroll
    for (int s = 0; s < 4; s++) {
        uint32_t ro = (uint32_t)((wid * 16) * 144) + (uint32_t)(s * 32);
        ldsm_x4(qh[s],  sb + aoff + ro);
        ldsm_x4(qlo[s], sb + ATEN_BYTES + aoff + ro);
    }

    // V trans lane offset: row = lane&7 (+8 if lane bit3), col-pair select by lane bit4
    const uint32_t voff = (uint32_t)(((lane & 7) + 8 * ((lane >> 3) & 1)) * 144 + ((lane >> 4) & 1) * 16);

    float m0 = -1e30f, m1 = -1e30f, l0 = 0.f, l1 = 0.f;
    float o[8][4];
    #pragma unroll
    for (int j = 0; j < 8; j++)
        #pragma unroll
        for (int t = 0; t < 4; t++) o[j][t] = 0.f;

    for (int it = 0; it < LL / 64; it++) {
        const int kt = it * 64;
        const int bb = it & 1;
        CP_WAIT0();            // K(it) ready
        __syncthreads();       // also publishes mask(it), frees V buffer
        load_v(kt);            // V(it) loads during S compute

        const uint32_t sKh = sb + (bb ? AOFF_K1 : AOFF_K0);
        const uint32_t sKl = sKh + ATEN_BYTES;

        // ---- S = Q K^T (bf16x3), x4 K loads serve two n-tiles ----
        float s[8][4];
        #pragma unroll
        for (int j = 0; j < 8; j++)
            #pragma unroll
            for (int t = 0; t < 4; t++) s[j][t] = 0.f;
        #pragma unroll
        for (int ks = 0; ks < 4; ks++) {
            #pragma unroll
            for (int jp = 0; jp < 4; jp++) {
                uint32_t k4h[4], k4l[4];
                uint32_t ro = (uint32_t)((16 * jp) * 144) + (uint32_t)(ks * 32);
                ldsm_x4(k4h, sKh + aoff + ro);
                ldsm_x4(k4l, sKl + aoff + ro);
                #pragma unroll
                for (int hf = 0; hf < 2; hf++) {
                    uint32_t bh[2] = { k4h[hf], k4h[hf + 2] };
                    uint32_t bl[2] = { k4l[hf], k4l[hf + 2] };
                    mma_bf16(s[2*jp + hf], qh[ks],  bh);
                    mma_bf16(s[2*jp + hf], qh[ks],  bl);
                    mma_bf16(s[2*jp + hf], qlo[ks], bh);
                }
            }
        }

        // ---- online softmax ----
        float mx0 = -1e30f, mx1 = -1e30f;
        #pragma unroll
        for (int j = 0; j < 8; j++) {
            float ma0 = maskadd[bb * 64 + 8 * j + 2 * qc];
            float ma1 = maskadd[bb * 64 + 8 * j + 2 * qc + 1];
            s[j][0] = s[j][0] * 0.125f + ma0;
            s[j][1] = s[j][1] * 0.125f + ma1;
            s[j][2] = s[j][2] * 0.125f + ma0;
            s[j][3] = s[j][3] * 0.125f + ma1;
            mx0 = fmaxf(mx0, fmaxf(s[j][0], s[j][1]));
            mx1 = fmaxf(mx1, fmaxf(s[j][2], s[j][3]));
        }
        mx0 = fmaxf(mx0, __shfl_xor_sync(0xffffffffu, mx0, 1));
        mx0 = fmaxf(mx0, __shfl_xor_sync(0xffffffffu, mx0, 2));
        mx1 = fmaxf(mx1, __shfl_xor_sync(0xffffffffu, mx1, 1));
        mx1 = fmaxf(mx1, __shfl_xor_sync(0xffffffffu, mx1, 2));
        float mn0 = fmaxf(m0, mx0), mn1 = fmaxf(m1, mx1);
        float c0 = __expf(m0 - mn0), c1 = __expf(m1 - mn1);
        m0 = mn0; m1 = mn1;
        float ls0 = 0.f, ls1 = 0.f;
        #pragma unroll
        for (int j = 0; j < 8; j++) {
            s[j][0] = __expf(s[j][0] - mn0);
            s[j][1] = __expf(s[j][1] - mn0);
            s[j][2] = __expf(s[j][2] - mn1);
            s[j][3] = __expf(s[j][3] - mn1);
            ls0 += s[j][0] + s[j][1];
            ls1 += s[j][2] + s[j][3];
        }
        l0 = l0 * c0 + ls0;
        l1 = l1 * c1 + ls1;
        #pragma unroll
        for (int j = 0; j < 8; j++) {
            o[j][0] *= c0; o[j][1] *= c0;
            o[j][2] *= c1; o[j][3] *= c1;
        }

        CP_WAIT0();            // V(it) ready
        __syncthreads();
        if (it + 1 < LL / 64) {
            load_k(kt + 64, 1 - bb);   // K(it+1) loads during PV compute
            if (tid < 64)
                maskadd[(1 - bb) * 64 + tid] =
                    (1.0f - (float)mask[b * LL + kt + 64 + tid]) * (-1e30f);
        }

        // ---- O += P @ V (bf16x3, x4.trans V loads serve two n-tiles) ----
        #pragma unroll
        for (int ks = 0; ks < 4; ks++) {
            uint32_t ph[4], pl[4];
            pack_hilo(ph[0], pl[0], s[2*ks][0],   s[2*ks][1]);
            pack_hilo(ph[1], pl[1], s[2*ks][2],   s[2*ks][3]);
            pack_hilo(ph[2], pl[2], s[2*ks+1][0], s[2*ks+1][1]);
            pack_hilo(ph[3], pl[3], s[2*ks+1][2], s[2*ks+1][3]);
            uint32_t vbase = sb + AOFF_V + voff + (uint32_t)((16 * ks) * 144);
            #pragma unroll
            for (int jp = 0; jp < 4; jp++) {
                uint32_t v4h[4], v4l[4];
                uint32_t vro = (uint32_t)(32 * jp);
                ldsm_x4_t(v4h, vbase + vro);
                ldsm_x4_t(v4l, vbase + ATEN_BYTES + vro);
                mma_bf16(o[2*jp],     ph, &v4h[0]);
                mma_bf16(o[2*jp],     ph, &v4l[0]);
                mma_bf16(o[2*jp],     pl, &v4h[0]);
                mma_bf16(o[2*jp + 1], ph, &v4h[2]);
                mma_bf16(o[2*jp + 1], ph, &v4l[2]);
                mma_bf16(o[2*jp + 1], pl, &v4h[2]);
            }
        }
    }

    // ---- finalize ----
    l0 += __shfl_xor_sync(0xffffffffu, l0, 1);
    l0 += __shfl_xor_sync(0xffffffffu, l0, 2);
    l1 += __shfl_xor_sync(0xffffffffu, l1, 1);
    l1 += __shfl_xor_sync(0xffffffffu, l1, 2);
    float i0 = 1.0f / l0, i1 = 1.0f / l1;

    const int row0 = q0 + wid * 16 + er;
    #pragma unroll
    for (int j = 0; j < 8; j++) {
        int col = h * DHH + 8 * j + 2 * qc;
        size_t base0 = (size_t)(b * LL + row0) * DD + col;
        size_t base1 = base0 + 8 * (size_t)DD;
        float2 r0, r1;
        r0.x = o[j][0] * i0 + x[base0];
        r0.y = o[j][1] * i0 + x[base0 + 1];
        r1.x = o[j][2] * i1 + x[base1];
        r1.y = o[j][3] * i1 + x[base1 + 1];
        *(float2*)&res[base0] = r0;
        *(float2*)&res[base1] = r1;
    }
}

// ---------------- launch ----------------
extern "C" void kernel_launch(void* const* d_in, const int* in_sizes, int n_in,
                              void* d_out, int out_size)
{
    const float* x    = (const float*)d_in[0];
    const int*   mask = (const int*)  d_in[1];
    const float* Wq   = (const float*)d_in[2];
    const float* bq   = (const float*)d_in[3];
    const float* Wk   = (const float*)d_in[4];
    const float* bk   = (const float*)d_in[5];
    const float* Wv   = (const float*)d_in[6];
    const float* bv   = (const float*)d_in[7];
    const float* g1   = (const float*)d_in[8];
    const float* b1   = (const float*)d_in[9];
    const float* g2   = (const float*)d_in[10];
    const float* b2   = (const float*)d_in[11];
    const float* Wo1  = (const float*)d_in[12];
    const float* bo1  = (const float*)d_in[13];
    const float* Wo2  = (const float*)d_in[14];
    const float* bo2  = (const float*)d_in[15];
    float* out = (float*)d_out;

    __nv_bfloat16 *hhi, *hlo, *qkvhi, *qkvlo, *ln2hi, *ln2lo, *mlphi, *mlplo;
    __nv_bfloat16 *wqkvhi, *wqkvlo, *w1hi, *w1lo, *w2hi, *w2lo;
    float *res_, *bqkv;
    cudaGetSymbolAddress((void**)&hhi,    g_h_hi);
    cudaGetSymbolAddress((void**)&hlo,    g_h_lo);
    cudaGetSymbolAddress((void**)&qkvhi,  g_qkv_hi);
    cudaGetSymbolAddress((void**)&qkvlo,  g_qkv_lo);
    cudaGetSymbolAddress((void**)&ln2hi,  g_ln2_hi);
    cudaGetSymbolAddress((void**)&ln2lo,  g_ln2_lo);
    cudaGetSymbolAddress((void**)&mlphi,  g_mlp_hi);
    cudaGetSymbolAddress((void**)&mlplo,  g_mlp_lo);
    cudaGetSymbolAddress((void**)&wqkvhi, g_wqkv_hi);
    cudaGetSymbolAddress((void**)&wqkvlo, g_wqkv_lo);
    cudaGetSymbolAddress((void**)&w1hi,   g_w1_hi);
    cudaGetSymbolAddress((void**)&w1lo,   g_w1_lo);
    cudaGetSymbolAddress((void**)&w2hi,   g_w2_hi);
    cudaGetSymbolAddress((void**)&w2lo,   g_w2_lo);
    cudaGetSymbolAddress((void**)&res_,   g_res);
    cudaGetSymbolAddress((void**)&bqkv,   g_bqkv);

    cudaFuncSetAttribute(bgemm_kernel<0, false, true>,  cudaFuncAttributeMaxDynamicSharedMemorySize, BGEMM_SMEM);
    cudaFuncSetAttribute(bgemm_kernel<1, false, true>,  cudaFuncAttributeMaxDynamicSharedMemorySize, BGEMM_SMEM);
    cudaFuncSetAttribute(bgemm_kernel<0, true,  false>, cudaFuncAttributeMaxDynamicSharedMemorySize, BGEMM_SMEM);
    cudaFuncSetAttribute(attn_mma_kernel, cudaFuncAttributeMaxDynamicSharedMemorySize, ATT2_SMEM);

    // 0) weight prep
    dim3 tb(32, 8), tg(32, 32);
    tsplit_kernel<<<tg, tb>>>(Wq,  wqkvhi + 0 * (size_t)DD * DD, wqkvlo + 0 * (size_t)DD * DD);
    tsplit_kernel<<<tg, tb>>>(Wk,  wqkvhi + 1 * (size_t)DD * DD, wqkvlo + 1 * (size_t)DD * DD);
    tsplit_kernel<<<tg, tb>>>(Wv,  wqkvhi + 2 * (size_t)DD * DD, wqkvlo + 2 * (size_t)DD * DD);
    tsplit_kernel<<<tg, tb>>>(Wo1, w1hi, w1lo);
    tsplit_kernel<<<tg, tb>>>(Wo2, w2hi, w2lo);
    cudaMemcpyAsync(bqkv,        bq, DD * sizeof(float), cudaMemcpyDeviceToDevice, 0);
    cudaMemcpyAsync(bqkv + DD,   bk, DD * sizeof(float), cudaMemcpyDeviceToDevice, 0);
    cudaMemcpyAsync(bqkv + 2*DD, bv, DD * sizeof(float), cudaMemcpyDeviceToDevice, 0);

    // 1) LN1 -> bf16 hi/lo
    ln_split_kernel<<<NTOK, 256>>>(x, g1, b1, hhi, hlo);

    // 2) fused QKV projection -> packed qkv bf16 hi/lo
    bgemm_kernel<0, false, true><<<dim3(D3 / 128, NTOK / 128), 256, BGEMM_SMEM>>>(
        hhi, hlo, wqkvhi, wqkvlo, bqkv, nullptr, nullptr, qkvhi, qkvlo, NTOK, D3, DD);

    // 3) flash attention + residual -> res (fp32)
    attn_mma_kernel<<<dim3(LL / 64, BB * HH), 128, ATT2_SMEM>>>(qkvhi, qkvlo, mask, x, res_);

    // 4) LN2 -> bf16 hi/lo
    ln_split_kernel<<<NTOK, 256>>>(res_, g2, b2, ln2hi, ln2lo);

    // 5) MLP up + GELU -> bf16 hi/lo
    bgemm_kernel<1, false, true><<<dim3(DD / 128, NTOK / 128), 256, BGEMM_SMEM>>>(
        ln2hi, ln2lo, w1hi, w1lo, bo1, nullptr, nullptr, mlphi, mlplo, NTOK, DD, DD);

    // 6) MLP down + bias + residual -> out (fp32)
    bgemm_kernel<0, true, false><<<dim3(DD / 128, NTOK / 128), 256, BGEMM_SMEM>>>(
        mlphi, mlplo, w2hi, w2lo, bo2, res_, out, nullptr, nullptr, NTOK, DD, DD);
}

// round 7
// speedup vs baseline: 1.7232x; 1.7232x over previous
#include <cuda_runtime.h>
#include <cuda.h>
#include <cuda_bf16.h>
#include <math.h>
#include <stdint.h>

#define BB 4
#define LL 2048
#define DD 1024
#define HH 16
#define DHH 64
#define NTOK (BB*LL)   // 8192 rows
#define D3  (3*DD)     // 3072

// ---------------- scratch (device globals; no allocation allowed) ----------------
__device__ __align__(16) __nv_bfloat16 g_h_hi  [NTOK*DD];
__device__ __align__(16) __nv_bfloat16 g_qkv_hi[NTOK*D3];
__device__ __align__(16) __nv_bfloat16 g_ln2_hi[NTOK*DD];
__device__ __align__(16) __nv_bfloat16 g_ln2_lo[NTOK*DD];
__device__ __align__(16) __nv_bfloat16 g_mlp_hi[NTOK*DD];
__device__ __align__(16) __nv_bfloat16 g_mlp_lo[NTOK*DD];
__device__ __align__(16) __nv_bfloat16 g_wqkv_hi[3*DD*DD];
__device__ __align__(16) __nv_bfloat16 g_w1_hi[DD*DD];
__device__ __align__(16) __nv_bfloat16 g_w1_lo[DD*DD];
__device__ __align__(16) __nv_bfloat16 g_w2_hi[DD*DD];
__device__ __align__(16) __nv_bfloat16 g_w2_lo[DD*DD];
__device__ __align__(16) float g_res [NTOK*DD];
__device__ __align__(16) float g_bqkv[D3];

// ============================ helpers ============================
__device__ __forceinline__ uint32_t smem_u32(const void* p) {
    uint32_t a;
    asm("{ .reg .u64 t; cvta.to.shared.u64 t, %1; cvt.u32.u64 %0, t; }" : "=r"(a) : "l"(p));
    return a;
}
__device__ __forceinline__ void mma_bf16(float* c, const uint32_t* a, const uint32_t* b) {
    asm volatile(
        "mma.sync.aligned.m16n8k16.row.col.f32.bf16.bf16.f32 "
        "{%0,%1,%2,%3}, {%4,%5,%6,%7}, {%8,%9}, {%0,%1,%2,%3};"
        : "+f"(c[0]), "+f"(c[1]), "+f"(c[2]), "+f"(c[3])
        : "r"(a[0]), "r"(a[1]), "r"(a[2]), "r"(a[3]), "r"(b[0]), "r"(b[1]));
}
__device__ __forceinline__ void ldsm_x4(uint32_t* r, uint32_t addr) {
    asm volatile("ldmatrix.sync.aligned.m8n8.x4.shared.b16 {%0,%1,%2,%3}, [%4];"
        : "=r"(r[0]), "=r"(r[1]), "=r"(r[2]), "=r"(r[3]) : "r"(addr));
}
__device__ __forceinline__ void ldsm_x4_t(uint32_t* r, uint32_t addr) {
    asm volatile("ldmatrix.sync.aligned.m8n8.x4.trans.shared.b16 {%0,%1,%2,%3}, [%4];"
        : "=r"(r[0]), "=r"(r[1]), "=r"(r[2]), "=r"(r[3]) : "r"(addr));
}
__device__ __forceinline__ void cp16(uint32_t dst, const void* src) {
    asm volatile("cp.async.cg.shared.global [%0], [%1], 16;" :: "r"(dst), "l"(src));
}
#define CP_COMMIT() asm volatile("cp.async.commit_group;" ::: "memory")
#define CP_WAIT0()  asm volatile("cp.async.wait_group 0;" ::: "memory")

__device__ __forceinline__ void cvt_store(__nv_bfloat16* hi, __nv_bfloat16* lo, float4 a) {
    __nv_bfloat162 h0 = __floats2bfloat162_rn(a.x, a.y);
    __nv_bfloat162 h1 = __floats2bfloat162_rn(a.z, a.w);
    *(__nv_bfloat162*)(hi)     = h0;
    *(__nv_bfloat162*)(hi + 2) = h1;
    if (lo) {
        __nv_bfloat162 l0 = __floats2bfloat162_rn(a.x - __bfloat162float(__low2bfloat16(h0)),
                                                  a.y - __bfloat162float(__high2bfloat16(h0)));
        __nv_bfloat162 l1 = __floats2bfloat162_rn(a.z - __bfloat162float(__low2bfloat16(h1)),
                                                  a.w - __bfloat162float(__high2bfloat16(h1)));
        *(__nv_bfloat162*)(lo)     = l0;
        *(__nv_bfloat162*)(lo + 2) = l1;
    }
}

// ============ bf16 GEMM, TERMS=1 (plain) or 3 (compensated) ============
// A [M,K], B [N,K] bf16 (hi[,lo]). 128x128 tile, BK=32, 8 warps (2x4).
// OUTM: 0 = fp32 (+optional residual), 1 = bf16 hi/lo split, 2 = bf16 hi only
#define GS_STRIDE 40
#define GT_BYTES  (128*GS_STRIDE*2)      // 10240

template<int ACT, bool RES, int OUTM, int TERMS>
__global__ void __launch_bounds__(256, 2)
bgemm_kernel(const __nv_bfloat16* __restrict__ Ah, const __nv_bfloat16* __restrict__ Al,
             const __nv_bfloat16* __restrict__ Bh, const __nv_bfloat16* __restrict__ Bl,
             const float* __restrict__ bias, const float* __restrict__ res,
             float* __restrict__ Cf, __nv_bfloat16* __restrict__ Ch,
             __nv_bfloat16* __restrict__ Cl, int M, int N, int K)
{
    constexpr int NT = (TERMS == 1) ? 2 : 4;
    constexpr uint32_t STAGE = NT * GT_BYTES;

    extern __shared__ char dsm[];
    const uint32_t sb = smem_u32(dsm);

    const int tid  = threadIdx.x;
    const int wid  = tid >> 5;
    const int lane = tid & 31;
    const int wm   = wid >> 2;
    const int wn   = wid & 3;
    const int row0 = blockIdx.y * 128;
    const int col0 = blockIdx.x * 128;

    float acc[4][4][4];
    #pragma unroll
    for (int i = 0; i < 4; i++)
        #pragma unroll
        for (int j = 0; j < 4; j++)
            #pragma unroll
            for (int q = 0; q < 4; q++) acc[i][j][q] = 0.f;

    const uint32_t aoff = (uint32_t)(((lane & 15) * GS_STRIDE + ((lane >> 4) & 1) * 8) * 2);
    const int nkt = K / 32;

    auto load_stage = [&](int i, int buf) {
        uint32_t s0 = sb + (uint32_t)buf * STAGE;
        int kt = i * 32;
        #pragma unroll
        for (int u = 0; u < 2; u++) {
            int c   = tid + u * 256;
            int row = c >> 2;
            int ch  = c & 3;
            uint32_t so = (uint32_t)(row * (GS_STRIDE * 2) + ch * 16);
            size_t ga = (size_t)(row0 + row) * K + kt + ch * 8;
            size_t gb = (size_t)(col0 + row) * K + kt + ch * 8;
            if (TERMS == 1) {
                cp16(s0 + 0 * GT_BYTES + so, Ah + ga);
                cp16(s0 + 1 * GT_BYTES + so, Bh + gb);
            } else {
                cp16(s0 + 0 * GT_BYTES + so, Ah + ga);
                cp16(s0 + 1 * GT_BYTES + so, Al + ga);
                cp16(s0 + 2 * GT_BYTES + so, Bh + gb);
                cp16(s0 + 3 * GT_BYTES + so, Bl + gb);
            }
        }
        CP_COMMIT();
    };

    load_stage(0, 0);

    for (int i = 0; i < nkt; i++) {
        const int b = i & 1;
        CP_WAIT0();
        __syncthreads();
        if (i + 1 < nkt) load_stage(i + 1, 1 - b);

        const uint32_t sAh = sb + (uint32_t)b * STAGE;
        const uint32_t sAl = sAh + GT_BYTES;                        // TERMS==3 only
        const uint32_t sBh = sAh + (TERMS == 1 ? 1 : 2) * GT_BYTES;
        const uint32_t sBl = sAh + 3 * GT_BYTES;

        #pragma unroll
        for (int ks = 0; ks < 32; ks += 16) {
            uint32_t ah[4][4], al[4][4];
            #pragma unroll
            for (int mt = 0; mt < 4; mt++) {
                uint32_t ro = (uint32_t)((wm * 64 + mt * 16) * (GS_STRIDE * 2)) + (uint32_t)(ks * 2);
                ldsm_x4(ah[mt], sAh + aoff + ro);
                if (TERMS == 3) ldsm_x4(al[mt], sAl + aoff + ro);
            }
            #pragma unroll
            for (int ntp = 0; ntp < 2; ntp++) {
                uint32_t b4h[4], b4l[4];
                uint32_t ro = (uint32_t)((wn * 32 + ntp * 16) * (GS_STRIDE * 2)) + (uint32_t)(ks * 2);
                ldsm_x4(b4h, sBh + aoff + ro);
                if (TERMS == 3) ldsm_x4(b4l, sBl + aoff + ro);
                #pragma unroll
                for (int hfn = 0; hfn < 2; hfn++) {
                    int nt = ntp * 2 + hfn;
                    uint32_t bh[2] = { b4h[hfn], b4h[hfn + 2] };
                    #pragma unroll
                    for (int mt = 0; mt < 4; mt++) {
                        mma_bf16(acc[mt][nt], ah[mt], bh);
                        if (TERMS == 3) {
                            uint32_t bl[2] = { b4l[hfn], b4l[hfn + 2] };
                            mma_bf16(acc[mt][nt], ah[mt], bl);
                            mma_bf16(acc[mt][nt], al[mt], bh);
                        }
                    }
                }
            }
        }
    }

    const int er = lane >> 2;
    const int ec = (lane & 3) * 2;
    #pragma unroll
    for (int mt = 0; mt < 4; mt++) {
        #pragma unroll
        for (int half = 0; half < 2; half++) {
            int row = row0 + wm * 64 + mt * 16 + er + half * 8;
            #pragma unroll
            for (int nt = 0; nt < 4; nt++) {
                int col = col0 + wn * 32 + nt * 8 + ec;
                float v0 = acc[mt][nt][half * 2 + 0] + bias[col];
                float v1 = acc[mt][nt][half * 2 + 1] + bias[col + 1];
                if (ACT == 1) {
                    v0 = 0.5f * v0 * (1.0f + erff(v0 * 0.70710678118654752f));
                    v1 = 0.5f * v1 * (1.0f + erff(v1 * 0.70710678118654752f));
                }
                if (RES) {
                    const float* rp = res + (size_t)row * N;
                    v0 += rp[col]; v1 += rp[col + 1];
                }
                if (OUTM == 0) {
                    float2 o; o.x = v0; o.y = v1;
                    *(float2*)(Cf + (size_t)row * N + col) = o;
                } else {
                    __nv_bfloat162 h2 = __floats2bfloat162_rn(v0, v1);
                    *(__nv_bfloat162*)(Ch + (size_t)row * N + col) = h2;
                    if (OUTM == 1) {
                        float f0 = __bfloat162float(__low2bfloat16(h2));
                        float f1 = __bfloat162float(__high2bfloat16(h2));
                        __nv_bfloat162 l2 = __floats2bfloat162_rn(v0 - f0, v1 - f1);
                        *(__nv_bfloat162*)(Cl + (size_t)row * N + col) = l2;
                    }
                }
            }
        }
    }
}

// ---------------- weight transpose + optional hi/lo split ----------------
__global__ void __launch_bounds__(256)
tsplit_kernel(const float* __restrict__ in, __nv_bfloat16* __restrict__ oh,
              __nv_bfloat16* __restrict__ ol)
{
    __shared__ float t[32][33];
    int bx = blockIdx.x * 32, by = blockIdx.y * 32;
    int x = bx + threadIdx.x;
    #pragma unroll
    for (int j = 0; j < 32; j += 8)
        t[threadIdx.y + j][threadIdx.x] = in[(size_t)(by + threadIdx.y + j) * DD + x];
    __syncthreads();
    int x2 = by + threadIdx.x;
    #pragma unroll
    for (int j = 0; j < 32; j += 8) {
        float v = t[threadIdx.x][threadIdx.y + j];
        size_t o = (size_t)(bx + threadIdx.y + j) * DD + x2;
        __nv_bfloat16 h = __float2bfloat16(v);
        oh[o] = h;
        if (ol) ol[o] = __float2bfloat16(v - __bfloat162float(h));
    }
}

// ---------------- LayerNorm -> bf16 hi (+optional lo) ----------------
__global__ void __launch_bounds__(256)
ln_split_kernel(const float* __restrict__ in, const float* __restrict__ gam,
                const float* __restrict__ bet, __nv_bfloat16* __restrict__ oh,
                __nv_bfloat16* __restrict__ ol)
{
    size_t base = (size_t)blockIdx.x * DD;
    int t4 = threadIdx.x * 4;
    float4 v = *(const float4*)&in[base + t4];
    float s  = v.x + v.y + v.z + v.w;
    float s2 = v.x*v.x + v.y*v.y + v.z*v.z + v.w*v.w;
    #pragma unroll
    for (int o = 16; o; o >>= 1) {
        s  += __shfl_xor_sync(0xffffffffu, s,  o);
        s2 += __shfl_xor_sync(0xffffffffu, s2, o);
    }
    __shared__ float rs[8], rs2[8];
    __shared__ float smu, srstd;
    int w = threadIdx.x >> 5, lane = threadIdx.x & 31;
    if (lane == 0) { rs[w] = s; rs2[w] = s2; }
    __syncthreads();
    if (threadIdx.x == 0) {
        float S = 0.f, S2 = 0.f;
        #pragma unroll
        for (int i = 0; i < 8; i++) { S += rs[i]; S2 += rs2[i]; }
        float mu  = S * (1.0f / DD);
        float var = S2 * (1.0f / DD) - mu * mu;
        smu = mu;
        srstd = rsqrtf(var + 1e-6f);
    }
    __syncthreads();
    float mu = smu, rstd = srstd;
    float4 g4 = *(const float4*)&gam[t4];
    float4 b4 = *(const float4*)&bet[t4];
    float4 o;
    o.x = (v.x - mu) * rstd * g4.x + b4.x;
    o.y = (v.y - mu) * rstd * g4.y + b4.y;
    o.z = (v.z - mu) * rstd * g4.z + b4.z;
    o.w = (v.w - mu) * rstd * g4.w + b4.w;
    cvt_store(oh + base + t4, ol ? ol + base + t4 : (__nv_bfloat16*)0, o);
}

// ============ plain-bf16 tensor-core flash attention, cp.async pipelined ============
// qkv packed [NTOK][3072] bf16: q +0, k +1024, v +2048.
#define ATSTRIDE 72
#define ATEN_BYTES (64*ATSTRIDE*2)   // 9216 per tensor
#define AOFF_K0 9216
#define AOFF_K1 18432
#define AOFF_V  27648
#define AOFF_M  36864
#define ATT2_SMEM (AOFF_M + 2*64*4)  // 37376

__global__ void __launch_bounds__(128, 4)
attn_mma_kernel(const __nv_bfloat16* __restrict__ qkv,
                const int* __restrict__ mask,
                const float* __restrict__ x, float* __restrict__ res)
{
    extern __shared__ char sm8[];
    const uint32_t sb = smem_u32(sm8);
    __nv_bfloat16* Qh = (__nv_bfloat16*)sm8;
    float* maskadd = (float*)(sm8 + AOFF_M);

    const int tid  = threadIdx.x;
    const int wid  = tid >> 5;
    const int lane = tid & 31;
    const int b    = blockIdx.y >> 4;
    const int h    = blockIdx.y & 15;
    const int q0   = blockIdx.x * 64;
    const int er   = lane >> 2;
    const int qc   = lane & 3;

    auto load_k = [&](int kt, int buf) {
        uint32_t s0 = sb + (buf ? AOFF_K1 : AOFF_K0);
        #pragma unroll
        for (int u = 0; u < 4; u++) {
            int c = tid + u * 128;
            int row = c >> 3, ch = c & 7;
            size_t g = (size_t)(b * LL + kt + row) * D3 + DD + h * DHH + ch * 8;
            cp16(s0 + (uint32_t)(row * 144 + ch * 16), qkv + g);
        }
        CP_COMMIT();
    };
    auto load_v = [&](int kt) {
        uint32_t s0 = sb + AOFF_V;
        #pragma unroll
        for (int u = 0; u < 4; u++) {
            int c = tid + u * 128;
            int row = c >> 3, ch = c & 7;
            size_t g = (size_t)(b * LL + kt + row) * D3 + 2 * DD + h * DHH + ch * 8;
            cp16(s0 + (uint32_t)(row * 144 + ch * 16), qkv + g);
        }
        CP_COMMIT();
    };

    // ---- prologue ----
    {
        int lr = tid >> 1, lc = (tid & 1) * 32;
        size_t gq = (size_t)(b * LL + q0 + lr) * D3 + h * DHH + lc;
        #pragma unroll
        for (int j = 0; j < 4; j++)
            *(uint4*)&Qh[lr * ATSTRIDE + lc + 8*j] = *(const uint4*)(qkv + gq + 8*j);
    }
    load_k(0, 0);
    if (tid < 64)
        maskadd[tid] = (1.0f - (float)mask[b * LL + tid]) * (-1e30f);
    __syncthreads();

    // ---- persistent Q fragments ----
    const uint32_t aoff = (uint32_t)(((lane & 15) * ATSTRIDE + ((lane >> 4) & 1) * 8) * 2);
    uint32_t qh[4][4];
    #pragma unroll
    for (int s = 0; s < 4; s++) {
        uint32_t ro = (uint32_t)((wid * 16) * 144) + (uint32_t)(s * 32);
        ldsm_x4(qh[s], sb + aoff + ro);
    }

    const uint32_t voff = (uint32_t)(((lane & 7) + 8 * ((lane >> 3) & 1)) * 144 + ((lane >> 4) & 1) * 16);

    float m0 = -1e30f, m1 = -1e30f, l0 = 0.f, l1 = 0.f;
    float o[8][4];
    #pragma unroll
    for (int j = 0; j < 8; j++)
        #pragma unroll
        for (int t = 0; t < 4; t++) o[j][t] = 0.f;

    for (int it = 0; it < LL / 64; it++) {
        const int kt = it * 64;
        const int bb = it & 1;
        CP_WAIT0();
        __syncthreads();
        load_v(kt);

        const uint32_t sKh = sb + (bb ? AOFF_K1 : AOFF_K0);

        // ---- S = Q K^T (plain bf16) ----
        float s[8][4];
        #pragma unroll
        for (int j = 0; j < 8; j++)
            #pragma unroll
            for (int t = 0; t < 4; t++) s[j][t] = 0.f;
        #pragma unroll
        for (int ks = 0; ks < 4; ks++) {
            #pragma unroll
            for (int jp = 0; jp < 4; jp++) {
                uint32_t k4h[4];
                uint32_t ro = (uint32_t)((16 * jp) * 144) + (uint32_t)(ks * 32);
                ldsm_x4(k4h, sKh + aoff + ro);
                #pragma unroll
                for (int hf = 0; hf < 2; hf++) {
                    uint32_t bh[2] = { k4h[hf], k4h[hf + 2] };
                    mma_bf16(s[2*jp + hf], qh[ks], bh);
                }
            }
        }

        // ---- online softmax ----
        float mx0 = -1e30f, mx1 = -1e30f;
        #pragma unroll
        for (int j = 0; j < 8; j++) {
            float ma0 = maskadd[bb * 64 + 8 * j + 2 * qc];
            float ma1 = maskadd[bb * 64 + 8 * j + 2 * qc + 1];
            s[j][0] = s[j][0] * 0.125f + ma0;
            s[j][1] = s[j][1] * 0.125f + ma1;
            s[j][2] = s[j][2] * 0.125f + ma0;
            s[j][3] = s[j][3] * 0.125f + ma1;
            mx0 = fmaxf(mx0, fmaxf(s[j][0], s[j][1]));
            mx1 = fmaxf(mx1, fmaxf(s[j][2], s[j][3]));
        }
        mx0 = fmaxf(mx0, __shfl_xor_sync(0xffffffffu, mx0, 1));
        mx0 = fmaxf(mx0, __shfl_xor_sync(0xffffffffu, mx0, 2));
        mx1 = fmaxf(mx1, __shfl_xor_sync(0xffffffffu, mx1, 1));
        mx1 = fmaxf(mx1, __shfl_xor_sync(0xffffffffu, mx1, 2));
        float mn0 = fmaxf(m0, mx0), mn1 = fmaxf(m1, mx1);
        float c0 = __expf(m0 - mn0), c1 = __expf(m1 - mn1);
        m0 = mn0; m1 = mn1;
        float ls0 = 0.f, ls1 = 0.f;
        #pragma unroll
        for (int j = 0; j < 8; j++) {
            s[j][0] = __expf(s[j][0] - mn0);
            s[j][1] = __expf(s[j][1] - mn0);
            s[j][2] = __expf(s[j][2] - mn1);
            s[j][3] = __expf(s[j][3] - mn1);
            ls0 += s[j][0] + s[j][1];
            ls1 += s[j][2] + s[j][3];
        }
        l0 = l0 * c0 + ls0;
        l1 = l1 * c1 + ls1;
        #pragma unroll
        for (int j = 0; j < 8; j++) {
            o[j][0] *= c0; o[j][1] *= c0;
            o[j][2] *= c1; o[j][3] *= c1;
        }

        CP_WAIT0();
        __syncthreads();
        if (it + 1 < LL / 64) {
            load_k(kt + 64, 1 - bb);
            if (tid < 64)
                maskadd[(1 - bb) * 64 + tid] =
                    (1.0f - (float)mask[b * LL + kt + 64 + tid]) * (-1e30f);
        }

        // ---- O += P @ V (plain bf16) ----
        #pragma unroll
        for (int ks = 0; ks < 4; ks++) {
            uint32_t ph[4];
            __nv_bfloat162 p0 = __floats2bfloat162_rn(s[2*ks][0],   s[2*ks][1]);
            __nv_bfloat162 p1 = __floats2bfloat162_rn(s[2*ks][2],   s[2*ks][3]);
            __nv_bfloat162 p2 = __floats2bfloat162_rn(s[2*ks+1][0], s[2*ks+1][1]);
            __nv_bfloat162 p3 = __floats2bfloat162_rn(s[2*ks+1][2], s[2*ks+1][3]);
            ph[0] = *(uint32_t*)&p0; ph[1] = *(uint32_t*)&p1;
            ph[2] = *(uint32_t*)&p2; ph[3] = *(uint32_t*)&p3;
            uint32_t vbase = sb + AOFF_V + voff + (uint32_t)((16 * ks) * 144);
            #pragma unroll
            for (int jp = 0; jp < 4; jp++) {
                uint32_t v4h[4];
                ldsm_x4_t(v4h, vbase + (uint32_t)(32 * jp));
                mma_bf16(o[2*jp],     ph, &v4h[0]);
                mma_bf16(o[2*jp + 1], ph, &v4h[2]);
            }
        }
    }

    // ---- finalize ----
    l0 += __shfl_xor_sync(0xffffffffu, l0, 1);
    l0 += __shfl_xor_sync(0xffffffffu, l0, 2);
    l1 += __shfl_xor_sync(0xffffffffu, l1, 1);
    l1 += __shfl_xor_sync(0xffffffffu, l1, 2);
    float i0 = 1.0f / l0, i1 = 1.0f / l1;

    const int row0 = q0 + wid * 16 + er;
    #pragma unroll
    for (int j = 0; j < 8; j++) {
        int col = h * DHH + 8 * j + 2 * qc;
        size_t base0 = (size_t)(b * LL + row0) * DD + col;
        size_t base1 = base0 + 8 * (size_t)DD;
        float2 r0, r1;
        r0.x = o[j][0] * i0 + x[base0];
        r0.y = o[j][1] * i0 + x[base0 + 1];
        r1.x = o[j][2] * i1 + x[base1];
        r1.y = o[j][3] * i1 + x[base1 + 1];
        *(float2*)&res[base0] = r0;
        *(float2*)&res[base1] = r1;
    }
}

// ---------------- launch ----------------
extern "C" void kernel_launch(void* const* d_in, const int* in_sizes, int n_in,
                              void* d_out, int out_size)
{
    const float* x    = (const float*)d_in[0];
    const int*   mask = (const int*)  d_in[1];
    const float* Wq   = (const float*)d_in[2];
    const float* bq   = (const float*)d_in[3];
    const float* Wk   = (const float*)d_in[4];
    const float* bk   = (const float*)d_in[5];
    const float* Wv   = (const float*)d_in[6];
    const float* bv   = (const float*)d_in[7];
    const float* g1   = (const float*)d_in[8];
    const float* b1   = (const float*)d_in[9];
    const float* g2   = (const float*)d_in[10];
    const float* b2   = (const float*)d_in[11];
    const float* Wo1  = (const float*)d_in[12];
    const float* bo1  = (const float*)d_in[13];
    const float* Wo2  = (const float*)d_in[14];
    const float* bo2  = (const float*)d_in[15];
    float* out = (float*)d_out;

    __nv_bfloat16 *hhi, *qkvhi, *ln2hi, *ln2lo, *mlphi, *mlplo;
    __nv_bfloat16 *wqkvhi, *w1hi, *w1lo, *w2hi, *w2lo;
    float *res_, *bqkv;
    cudaGetSymbolAddress((void**)&hhi,    g_h_hi);
    cudaGetSymbolAddress((void**)&qkvhi,  g_qkv_hi);
    cudaGetSymbolAddress((void**)&ln2hi,  g_ln2_hi);
    cudaGetSymbolAddress((void**)&ln2lo,  g_ln2_lo);
    cudaGetSymbolAddress((void**)&mlphi,  g_mlp_hi);
    cudaGetSymbolAddress((void**)&mlplo,  g_mlp_lo);
    cudaGetSymbolAddress((void**)&wqkvhi, g_wqkv_hi);
    cudaGetSymbolAddress((void**)&w1hi,   g_w1_hi);
    cudaGetSymbolAddress((void**)&w1lo,   g_w1_lo);
    cudaGetSymbolAddress((void**)&w2hi,   g_w2_hi);
    cudaGetSymbolAddress((void**)&w2lo,   g_w2_lo);
    cudaGetSymbolAddress((void**)&res_,   g_res);
    cudaGetSymbolAddress((void**)&bqkv,   g_bqkv);

    const int SM1 = 2 * 2 * GT_BYTES;   // TERMS=1: 40960
    const int SM3 = 2 * 4 * GT_BYTES;   // TERMS=3: 81920
    cudaFuncSetAttribute(bgemm_kernel<0, false, 2, 1>, cudaFuncAttributeMaxDynamicSharedMemorySize, SM1);
    cudaFuncSetAttribute(bgemm_kernel<1, false, 1, 3>, cudaFuncAttributeMaxDynamicSharedMemorySize, SM3);
    cudaFuncSetAttribute(bgemm_kernel<0, true,  0, 3>, cudaFuncAttributeMaxDynamicSharedMemorySize, SM3);
    cudaFuncSetAttribute(attn_mma_kernel, cudaFuncAttributeMaxDynamicSharedMemorySize, ATT2_SMEM);

    // 0) weight prep
    dim3 tb(32, 8), tg(32, 32);
    tsplit_kernel<<<tg, tb>>>(Wq,  wqkvhi + 0 * (size_t)DD * DD, nullptr);
    tsplit_kernel<<<tg, tb>>>(Wk,  wqkvhi + 1 * (size_t)DD * DD, nullptr);
    tsplit_kernel<<<tg, tb>>>(Wv,  wqkvhi + 2 * (size_t)DD * DD, nullptr);
    tsplit_kernel<<<tg, tb>>>(Wo1, w1hi, w1lo);
    tsplit_kernel<<<tg, tb>>>(Wo2, w2hi, w2lo);
    cudaMemcpyAsync(bqkv,        bq, DD * sizeof(float), cudaMemcpyDeviceToDevice, 0);
    cudaMemcpyAsync(bqkv + DD,   bk, DD * sizeof(float), cudaMemcpyDeviceToDevice, 0);
    cudaMemcpyAsync(bqkv + 2*DD, bv, DD * sizeof(float), cudaMemcpyDeviceToDevice, 0);

    // 1) LN1 -> bf16 (hi only; feeds low-precision attention branch)
    ln_split_kernel<<<NTOK, 256>>>(x, g1, b1, hhi, nullptr);

    // 2) fused QKV projection, plain bf16 -> packed qkv bf16
    bgemm_kernel<0, false, 2, 1><<<dim3(D3 / 128, NTOK / 128), 256, SM1>>>(
        hhi, nullptr, wqkvhi, nullptr, bqkv, nullptr, nullptr, qkvhi, nullptr, NTOK, D3, DD);

    // 3) flash attention (plain bf16) + residual -> res (fp32)
    attn_mma_kernel<<<dim3(LL / 64, BB * HH), 128, ATT2_SMEM>>>(qkvhi, mask, x, res_);

    // 4) LN2 -> bf16 hi/lo (precision-critical path)
    ln_split_kernel<<<NTOK, 256>>>(res_, g2, b2, ln2hi, ln2lo);

    // 5) MLP up + GELU (bf16x3) -> bf16 hi/lo
    bgemm_kernel<1, false, 1, 3><<<dim3(DD / 128, NTOK / 128), 256, SM3>>>(
        ln2hi, ln2lo, w1hi, w1lo, bo1, nullptr, nullptr, mlphi, mlplo, NTOK, DD, DD);

    // 6) MLP down + bias + residual (bf16x3) -> out (fp32)
    bgemm_kernel<0, true, 0, 3><<<dim3(DD / 128, NTOK / 128), 256, SM3>>>(
        mlphi, mlplo, w2hi, w2lo, bo2, res_, out, nullptr, nullptr, NTOK, DD, DD);
}

// round 8
// speedup vs baseline: 2.3278x; 1.3509x over previous
#include <cuda_runtime.h>
#include <cuda.h>
#include <cuda_fp16.h>
#include <math.h>
#include <stdint.h>

#define BB 4
#define LL 2048
#define DD 1024
#define HH 16
#define DHH 64
#define NTOK (BB*LL)   // 8192 rows
#define D3  (3*DD)     // 3072

// ---------------- scratch (device globals; no allocation allowed) ----------------
__device__ __align__(16) __half g_h   [NTOK*DD];
__device__ __align__(16) __half g_qkv [NTOK*D3];
__device__ __align__(16) __half g_ln2 [NTOK*DD];
__device__ __align__(16) __half g_mlp [NTOK*DD];
__device__ __align__(16) __half g_wqkv[3*DD*DD];
__device__ __align__(16) __half g_w1  [DD*DD];
__device__ __align__(16) __half g_w2  [DD*DD];
__device__ __align__(16) float  g_res [NTOK*DD];
__device__ __align__(16) float  g_bqkv[D3];

// ============================ helpers ============================
__device__ __forceinline__ uint32_t smem_u32(const void* p) {
    uint32_t a;
    asm("{ .reg .u64 t; cvta.to.shared.u64 t, %1; cvt.u32.u64 %0, t; }" : "=r"(a) : "l"(p));
    return a;
}
__device__ __forceinline__ void mma_f16(float* c, const uint32_t* a, const uint32_t* b) {
    asm volatile(
        "mma.sync.aligned.m16n8k16.row.col.f32.f16.f16.f32 "
        "{%0,%1,%2,%3}, {%4,%5,%6,%7}, {%8,%9}, {%0,%1,%2,%3};"
        : "+f"(c[0]), "+f"(c[1]), "+f"(c[2]), "+f"(c[3])
        : "r"(a[0]), "r"(a[1]), "r"(a[2]), "r"(a[3]), "r"(b[0]), "r"(b[1]));
}
__device__ __forceinline__ void ldsm_x4(uint32_t* r, uint32_t addr) {
    asm volatile("ldmatrix.sync.aligned.m8n8.x4.shared.b16 {%0,%1,%2,%3}, [%4];"
        : "=r"(r[0]), "=r"(r[1]), "=r"(r[2]), "=r"(r[3]) : "r"(addr));
}
__device__ __forceinline__ void ldsm_x4_t(uint32_t* r, uint32_t addr) {
    asm volatile("ldmatrix.sync.aligned.m8n8.x4.trans.shared.b16 {%0,%1,%2,%3}, [%4];"
        : "=r"(r[0]), "=r"(r[1]), "=r"(r[2]), "=r"(r[3]) : "r"(addr));
}
__device__ __forceinline__ void cp16(uint32_t dst, const void* src) {
    asm volatile("cp.async.cg.shared.global [%0], [%1], 16;" :: "r"(dst), "l"(src));
}
#define CP_COMMIT() asm volatile("cp.async.commit_group;" ::: "memory")
#define CP_WAIT0()  asm volatile("cp.async.wait_group 0;" ::: "memory")

// ============ plain fp16 tensor-core GEMM, cp.async double-buffered ============
// A [M,K], B [N,K] fp16. 128x128 tile, BK=32, 8 warps (2x4).
// OUTM: 0 = fp32 (+optional residual), 2 = fp16
#define GS_STRIDE 40
#define GT_BYTES  (128*GS_STRIDE*2)      // 10240
#define GSTAGE    (2*GT_BYTES)           // A + B
#define HGEMM_SMEM (2*GSTAGE)            // 40960

template<int ACT, bool RES, int OUTM>
__global__ void __launch_bounds__(256, 2)
hgemm_kernel(const __half* __restrict__ A, const __half* __restrict__ B,
             const float* __restrict__ bias, const float* __restrict__ res,
             float* __restrict__ Cf, __half* __restrict__ Ch,
             int M, int N, int K)
{
    extern __shared__ char dsm[];
    const uint32_t sb = smem_u32(dsm);

    const int tid  = threadIdx.x;
    const int wid  = tid >> 5;
    const int lane = tid & 31;
    const int wm   = wid >> 2;
    const int wn   = wid & 3;
    const int row0 = blockIdx.y * 128;
    const int col0 = blockIdx.x * 128;

    float acc[4][4][4];
    #pragma unroll
    for (int i = 0; i < 4; i++)
        #pragma unroll
        for (int j = 0; j < 4; j++)
            #pragma unroll
            for (int q = 0; q < 4; q++) acc[i][j][q] = 0.f;

    const uint32_t aoff = (uint32_t)(((lane & 15) * GS_STRIDE + ((lane >> 4) & 1) * 8) * 2);
    const int nkt = K / 32;

    auto load_stage = [&](int i, int buf) {
        uint32_t s0 = sb + (uint32_t)buf * GSTAGE;
        int kt = i * 32;
        #pragma unroll
        for (int u = 0; u < 2; u++) {
            int c   = tid + u * 256;
            int row = c >> 2;
            int ch  = c & 3;
            uint32_t so = (uint32_t)(row * (GS_STRIDE * 2) + ch * 16);
            cp16(s0 + so,            A + (size_t)(row0 + row) * K + kt + ch * 8);
            cp16(s0 + GT_BYTES + so, B + (size_t)(col0 + row) * K + kt + ch * 8);
        }
        CP_COMMIT();
    };

    load_stage(0, 0);

    for (int i = 0; i < nkt; i++) {
        const int b = i & 1;
        CP_WAIT0();
        __syncthreads();
        if (i + 1 < nkt) load_stage(i + 1, 1 - b);

        const uint32_t sA = sb + (uint32_t)b * GSTAGE;
        const uint32_t sB = sA + GT_BYTES;

        #pragma unroll
        for (int ks = 0; ks < 32; ks += 16) {
            uint32_t ah[4][4];
            #pragma unroll
            for (int mt = 0; mt < 4; mt++) {
                uint32_t ro = (uint32_t)((wm * 64 + mt * 16) * (GS_STRIDE * 2)) + (uint32_t)(ks * 2);
                ldsm_x4(ah[mt], sA + aoff + ro);
            }
            #pragma unroll
            for (int ntp = 0; ntp < 2; ntp++) {
                uint32_t b4[4];
                uint32_t ro = (uint32_t)((wn * 32 + ntp * 16) * (GS_STRIDE * 2)) + (uint32_t)(ks * 2);
                ldsm_x4(b4, sB + aoff + ro);
                #pragma unroll
                for (int hfn = 0; hfn < 2; hfn++) {
                    int nt = ntp * 2 + hfn;
                    uint32_t bh[2] = { b4[hfn], b4[hfn + 2] };
                    #pragma unroll
                    for (int mt = 0; mt < 4; mt++)
                        mma_f16(acc[mt][nt], ah[mt], bh);
                }
            }
        }
    }

    const int er = lane >> 2;
    const int ec = (lane & 3) * 2;
    #pragma unroll
    for (int mt = 0; mt < 4; mt++) {
        #pragma unroll
        for (int half = 0; half < 2; half++) {
            int row = row0 + wm * 64 + mt * 16 + er + half * 8;
            #pragma unroll
            for (int nt = 0; nt < 4; nt++) {
                int col = col0 + wn * 32 + nt * 8 + ec;
                float v0 = acc[mt][nt][half * 2 + 0] + bias[col];
                float v1 = acc[mt][nt][half * 2 + 1] + bias[col + 1];
                if (ACT == 1) {
                    v0 = 0.5f * v0 * (1.0f + erff(v0 * 0.70710678118654752f));
                    v1 = 0.5f * v1 * (1.0f + erff(v1 * 0.70710678118654752f));
                }
                if (RES) {
                    const float* rp = res + (size_t)row * N;
                    v0 += rp[col]; v1 += rp[col + 1];
                }
                if (OUTM == 0) {
                    float2 o; o.x = v0; o.y = v1;
                    *(float2*)(Cf + (size_t)row * N + col) = o;
                } else {
                    __half2 h2 = __floats2half2_rn(v0, v1);
                    *(__half2*)(Ch + (size_t)row * N + col) = h2;
                }
            }
        }
    }
}

// ---------------- weight transpose -> fp16: out[n][k] = f16(in[k][n]) ----------------
__global__ void __launch_bounds__(256)
tsplit_kernel(const float* __restrict__ in, __half* __restrict__ oh)
{
    __shared__ float t[32][33];
    int bx = blockIdx.x * 32, by = blockIdx.y * 32;
    int x = bx + threadIdx.x;
    #pragma unroll
    for (int j = 0; j < 32; j += 8)
        t[threadIdx.y + j][threadIdx.x] = in[(size_t)(by + threadIdx.y + j) * DD + x];
    __syncthreads();
    int x2 = by + threadIdx.x;
    #pragma unroll
    for (int j = 0; j < 32; j += 8)
        oh[(size_t)(bx + threadIdx.y + j) * DD + x2] = __float2half(t[threadIdx.x][threadIdx.y + j]);
}

// ---------------- LayerNorm -> fp16 ----------------
__global__ void __launch_bounds__(256)
ln_half_kernel(const float* __restrict__ in, const float* __restrict__ gam,
               const float* __restrict__ bet, __half* __restrict__ oh)
{
    size_t base = (size_t)blockIdx.x * DD;
    int t4 = threadIdx.x * 4;
    float4 v = *(const float4*)&in[base + t4];
    float s  = v.x + v.y + v.z + v.w;
    float s2 = v.x*v.x + v.y*v.y + v.z*v.z + v.w*v.w;
    #pragma unroll
    for (int o = 16; o; o >>= 1) {
        s  += __shfl_xor_sync(0xffffffffu, s,  o);
        s2 += __shfl_xor_sync(0xffffffffu, s2, o);
    }
    __shared__ float rs[8], rs2[8];
    __shared__ float smu, srstd;
    int w = threadIdx.x >> 5, lane = threadIdx.x & 31;
    if (lane == 0) { rs[w] = s; rs2[w] = s2; }
    __syncthreads();
    if (threadIdx.x == 0) {
        float S = 0.f, S2 = 0.f;
        #pragma unroll
        for (int i = 0; i < 8; i++) { S += rs[i]; S2 += rs2[i]; }
        float mu  = S * (1.0f / DD);
        float var = S2 * (1.0f / DD) - mu * mu;
        smu = mu;
        srstd = rsqrtf(var + 1e-6f);
    }
    __syncthreads();
    float mu = smu, rstd = srstd;
    float4 g4 = *(const float4*)&gam[t4];
    float4 b4 = *(const float4*)&bet[t4];
    __half2 h0 = __floats2half2_rn((v.x - mu) * rstd * g4.x + b4.x,
                                   (v.y - mu) * rstd * g4.y + b4.y);
    __half2 h1 = __floats2half2_rn((v.z - mu) * rstd * g4.z + b4.z,
                                   (v.w - mu) * rstd * g4.w + b4.w);
    *(__half2*)(oh + base + t4)     = h0;
    *(__half2*)(oh + base + t4 + 2) = h1;
}

// ============ fp16 tensor-core flash attention, cp.async pipelined ============
// qkv packed [NTOK][3072] fp16: q +0, k +1024, v +2048.
#define ATSTRIDE 72
#define ATEN_BYTES (64*ATSTRIDE*2)   // 9216 per tensor
#define AOFF_K0 9216
#define AOFF_K1 18432
#define AOFF_V  27648
#define AOFF_M  36864
#define ATT2_SMEM (AOFF_M + 2*64*4)  // 37376

__global__ void __launch_bounds__(128, 4)
attn_mma_kernel(const __half* __restrict__ qkv,
                const int* __restrict__ mask,
                const float* __restrict__ x, float* __restrict__ res)
{
    extern __shared__ char sm8[];
    const uint32_t sb = smem_u32(sm8);
    __half* Qh = (__half*)sm8;
    float* maskadd = (float*)(sm8 + AOFF_M);

    const int tid  = threadIdx.x;
    const int wid  = tid >> 5;
    const int lane = tid & 31;
    const int b    = blockIdx.y >> 4;
    const int h    = blockIdx.y & 15;
    const int q0   = blockIdx.x * 64;
    const int er   = lane >> 2;
    const int qc   = lane & 3;

    auto load_k = [&](int kt, int buf) {
        uint32_t s0 = sb + (buf ? AOFF_K1 : AOFF_K0);
        #pragma unroll
        for (int u = 0; u < 4; u++) {
            int c = tid + u * 128;
            int row = c >> 3, ch = c & 7;
            size_t g = (size_t)(b * LL + kt + row) * D3 + DD + h * DHH + ch * 8;
            cp16(s0 + (uint32_t)(row * 144 + ch * 16), qkv + g);
        }
        CP_COMMIT();
    };
    auto load_v = [&](int kt) {
        uint32_t s0 = sb + AOFF_V;
        #pragma unroll
        for (int u = 0; u < 4; u++) {
            int c = tid + u * 128;
            int row = c >> 3, ch = c & 7;
            size_t g = (size_t)(b * LL + kt + row) * D3 + 2 * DD + h * DHH + ch * 8;
            cp16(s0 + (uint32_t)(row * 144 + ch * 16), qkv + g);
        }
        CP_COMMIT();
    };

    // ---- prologue ----
    {
        int lr = tid >> 1, lc = (tid & 1) * 32;
        size_t gq = (size_t)(b * LL + q0 + lr) * D3 + h * DHH + lc;
        #pragma unroll
        for (int j = 0; j < 4; j++)
            *(uint4*)&Qh[lr * ATSTRIDE + lc + 8*j] = *(const uint4*)(qkv + gq + 8*j);
    }
    load_k(0, 0);
    if (tid < 64)
        maskadd[tid] = (1.0f - (float)mask[b * LL + tid]) * (-1e30f);
    __syncthreads();

    // ---- persistent Q fragments ----
    const uint32_t aoff = (uint32_t)(((lane & 15) * ATSTRIDE + ((lane >> 4) & 1) * 8) * 2);
    uint32_t qh[4][4];
    #pragma unroll
    for (int s = 0; s < 4; s++) {
        uint32_t ro = (uint32_t)((wid * 16) * 144) + (uint32_t)(s * 32);
        ldsm_x4(qh[s], sb + aoff + ro);
    }

    const uint32_t voff = (uint32_t)(((lane & 7) + 8 * ((lane >> 3) & 1)) * 144 + ((lane >> 4) & 1) * 16);

    float m0 = -1e30f, m1 = -1e30f, l0 = 0.f, l1 = 0.f;
    float o[8][4];
    #pragma unroll
    for (int j = 0; j < 8; j++)
        #pragma unroll
        for (int t = 0; t < 4; t++) o[j][t] = 0.f;

    for (int it = 0; it < LL / 64; it++) {
        const int kt = it * 64;
        const int bb = it & 1;
        CP_WAIT0();
        __syncthreads();
        load_v(kt);

        const uint32_t sKh = sb + (bb ? AOFF_K1 : AOFF_K0);

        // ---- S = Q K^T ----
        float s[8][4];
        #pragma unroll
        for (int j = 0; j < 8; j++)
            #pragma unroll
            for (int t = 0; t < 4; t++) s[j][t] = 0.f;
        #pragma unroll
        for (int ks = 0; ks < 4; ks++) {
            #pragma unroll
            for (int jp = 0; jp < 4; jp++) {
                uint32_t k4[4];
                uint32_t ro = (uint32_t)((16 * jp) * 144) + (uint32_t)(ks * 32);
                ldsm_x4(k4, sKh + aoff + ro);
                #pragma unroll
                for (int hf = 0; hf < 2; hf++) {
                    uint32_t bh[2] = { k4[hf], k4[hf + 2] };
                    mma_f16(s[2*jp + hf], qh[ks], bh);
                }
            }
        }

        // ---- online softmax ----
        float mx0 = -1e30f, mx1 = -1e30f;
        #pragma unroll
        for (int j = 0; j < 8; j++) {
            float ma0 = maskadd[bb * 64 + 8 * j + 2 * qc];
            float ma1 = maskadd[bb * 64 + 8 * j + 2 * qc + 1];
            s[j][0] = s[j][0] * 0.125f + ma0;
            s[j][1] = s[j][1] * 0.125f + ma1;
            s[j][2] = s[j][2] * 0.125f + ma0;
            s[j][3] = s[j][3] * 0.125f + ma1;
            mx0 = fmaxf(mx0, fmaxf(s[j][0], s[j][1]));
            mx1 = fmaxf(mx1, fmaxf(s[j][2], s[j][3]));
        }
        mx0 = fmaxf(mx0, __shfl_xor_sync(0xffffffffu, mx0, 1));
        mx0 = fmaxf(mx0, __shfl_xor_sync(0xffffffffu, mx0, 2));
        mx1 = fmaxf(mx1, __shfl_xor_sync(0xffffffffu, mx1, 1));
        mx1 = fmaxf(mx1, __shfl_xor_sync(0xffffffffu, mx1, 2));
        float mn0 = fmaxf(m0, mx0), mn1 = fmaxf(m1, mx1);
        float c0 = __expf(m0 - mn0), c1 = __expf(m1 - mn1);
        m0 = mn0; m1 = mn1;
        float ls0 = 0.f, ls1 = 0.f;
        #pragma unroll
        for (int j = 0; j < 8; j++) {
            s[j][0] = __expf(s[j][0] - mn0);
            s[j][1] = __expf(s[j][1] - mn0);
            s[j][2] = __expf(s[j][2] - mn1);
            s[j][3] = __expf(s[j][3] - mn1);
            ls0 += s[j][0] + s[j][1];
            ls1 += s[j][2] + s[j][3];
        }
        l0 = l0 * c0 + ls0;
        l1 = l1 * c1 + ls1;
        #pragma unroll
        for (int j = 0; j < 8; j++) {
            o[j][0] *= c0; o[j][1] *= c0;
            o[j][2] *= c1; o[j][3] *= c1;
        }

        CP_WAIT0();
        __syncthreads();
        if (it + 1 < LL / 64) {
            load_k(kt + 64, 1 - bb);
            if (tid < 64)
                maskadd[(1 - bb) * 64 + tid] =
                    (1.0f - (float)mask[b * LL + kt + 64 + tid]) * (-1e30f);
        }

        // ---- O += P @ V ----
        #pragma unroll
        for (int ks = 0; ks < 4; ks++) {
            uint32_t ph[4];
            __half2 p0 = __floats2half2_rn(s[2*ks][0],   s[2*ks][1]);
            __half2 p1 = __floats2half2_rn(s[2*ks][2],   s[2*ks][3]);
            __half2 p2 = __floats2half2_rn(s[2*ks+1][0], s[2*ks+1][1]);
            __half2 p3 = __floats2half2_rn(s[2*ks+1][2], s[2*ks+1][3]);
            ph[0] = *(uint32_t*)&p0; ph[1] = *(uint32_t*)&p1;
            ph[2] = *(uint32_t*)&p2; ph[3] = *(uint32_t*)&p3;
            uint32_t vbase = sb + AOFF_V + voff + (uint32_t)((16 * ks) * 144);
            #pragma unroll
            for (int jp = 0; jp < 4; jp++) {
                uint32_t v4[4];
                ldsm_x4_t(v4, vbase + (uint32_t)(32 * jp));
                mma_f16(o[2*jp],     ph, &v4[0]);
                mma_f16(o[2*jp + 1], ph, &v4[2]);
            }
        }
    }

    // ---- finalize ----
    l0 += __shfl_xor_sync(0xffffffffu, l0, 1);
    l0 += __shfl_xor_sync(0xffffffffu, l0, 2);
    l1 += __shfl_xor_sync(0xffffffffu, l1, 1);
    l1 += __shfl_xor_sync(0xffffffffu, l1, 2);
    float i0 = 1.0f / l0, i1 = 1.0f / l1;

    const int row0 = q0 + wid * 16 + er;
    #pragma unroll
    for (int j = 0; j < 8; j++) {
        int col = h * DHH + 8 * j + 2 * qc;
        size_t base0 = (size_t)(b * LL + row0) * DD + col;
        size_t base1 = base0 + 8 * (size_t)DD;
        float2 r0, r1;
        r0.x = o[j][0] * i0 + x[base0];
        r0.y = o[j][1] * i0 + x[base0 + 1];
        r1.x = o[j][2] * i1 + x[base1];
        r1.y = o[j][3] * i1 + x[base1 + 1];
        *(float2*)&res[base0] = r0;
        *(float2*)&res[base1] = r1;
    }
}

// ---------------- launch ----------------
extern "C" void kernel_launch(void* const* d_in, const int* in_sizes, int n_in,
                              void* d_out, int out_size)
{
    const float* x    = (const float*)d_in[0];
    const int*   mask = (const int*)  d_in[1];
    const float* Wq   = (const float*)d_in[2];
    const float* bq   = (const float*)d_in[3];
    const float* Wk   = (const float*)d_in[4];
    const float* bk   = (const float*)d_in[5];
    const float* Wv   = (const float*)d_in[6];
    const float* bv   = (const float*)d_in[7];
    const float* g1   = (const float*)d_in[8];
    const float* b1   = (const float*)d_in[9];
    const float* g2   = (const float*)d_in[10];
    const float* b2   = (const float*)d_in[11];
    const float* Wo1  = (const float*)d_in[12];
    const float* bo1  = (const float*)d_in[13];
    const float* Wo2  = (const float*)d_in[14];
    const float* bo2  = (const float*)d_in[15];
    float* out = (float*)d_out;

    __half *h_, *qkv_, *ln2_, *mlp_, *wqkv_, *w1_, *w2_;
    float *res_, *bqkv;
    cudaGetSymbolAddress((void**)&h_,    g_h);
    cudaGetSymbolAddress((void**)&qkv_,  g_qkv);
    cudaGetSymbolAddress((void**)&ln2_,  g_ln2);
    cudaGetSymbolAddress((void**)&mlp_,  g_mlp);
    cudaGetSymbolAddress((void**)&wqkv_, g_wqkv);
    cudaGetSymbolAddress((void**)&w1_,   g_w1);
    cudaGetSymbolAddress((void**)&w2_,   g_w2);
    cudaGetSymbolAddress((void**)&res_,  g_res);
    cudaGetSymbolAddress((void**)&bqkv,  g_bqkv);

    cudaFuncSetAttribute(hgemm_kernel<0, false, 2>, cudaFuncAttributeMaxDynamicSharedMemorySize, HGEMM_SMEM);
    cudaFuncSetAttribute(hgemm_kernel<1, false, 2>, cudaFuncAttributeMaxDynamicSharedMemorySize, HGEMM_SMEM);
    cudaFuncSetAttribute(hgemm_kernel<0, true,  0>, cudaFuncAttributeMaxDynamicSharedMemorySize, HGEMM_SMEM);
    cudaFuncSetAttribute(attn_mma_kernel, cudaFuncAttributeMaxDynamicSharedMemorySize, ATT2_SMEM);

    // 0) weight prep: transpose -> fp16 [N][K]; bias concat
    dim3 tb(32, 8), tg(32, 32);
    tsplit_kernel<<<tg, tb>>>(Wq,  wqkv_ + 0 * (size_t)DD * DD);
    tsplit_kernel<<<tg, tb>>>(Wk,  wqkv_ + 1 * (size_t)DD * DD);
    tsplit_kernel<<<tg, tb>>>(Wv,  wqkv_ + 2 * (size_t)DD * DD);
    tsplit_kernel<<<tg, tb>>>(Wo1, w1_);
    tsplit_kernel<<<tg, tb>>>(Wo2, w2_);
    cudaMemcpyAsync(bqkv,        bq, DD * sizeof(float), cudaMemcpyDeviceToDevice, 0);
    cudaMemcpyAsync(bqkv + DD,   bk, DD * sizeof(float), cudaMemcpyDeviceToDevice, 0);
    cudaMemcpyAsync(bqkv + 2*DD, bv, DD * sizeof(float), cudaMemcpyDeviceToDevice, 0);

    // 1) LN1 -> fp16
    ln_half_kernel<<<NTOK, 256>>>(x, g1, b1, h_);

    // 2) fused QKV projection -> packed qkv fp16
    hgemm_kernel<0, false, 2><<<dim3(D3 / 128, NTOK / 128), 256, HGEMM_SMEM>>>(
        h_, wqkv_, bqkv, nullptr, nullptr, qkv_, NTOK, D3, DD);

    // 3) flash attention + residual -> res (fp32)
    attn_mma_kernel<<<dim3(LL / 64, BB * HH), 128, ATT2_SMEM>>>(qkv_, mask, x, res_);

    // 4) LN2 -> fp16
    ln_half_kernel<<<NTOK, 256>>>(res_, g2, b2, ln2_);

    // 5) MLP up + GELU -> fp16
    hgemm_kernel<1, false, 2><<<dim3(DD / 128, NTOK / 128), 256, HGEMM_SMEM>>>(
        ln2_, w1_, bo1, nullptr, nullptr, mlp_, NTOK, DD, DD);

    // 6) MLP down + bias + residual -> out (fp32)
    hgemm_kernel<0, true, 0><<<dim3(DD / 128, NTOK / 128), 256, HGEMM_SMEM>>>(
        mlp_, w2_, bo2, res_, out, nullptr, NTOK, DD, DD);
}